// round 3
// baseline (speedup 1.0000x reference)
#include <cuda_runtime.h>
#include <math.h>

#define Bc 4
#define Sc 2048
#define Ec 128
#define Hc 4
#define HDc 32
#define Mc (Bc*Sc)            // 8192 tokens
#define SSs ((size_t)Sc*(size_t)Sc)

// ---------------- scratch (device globals: allocation-free) ----------------
__device__ float g_cat[Mc*512];   // [M,512] gated concat input
__device__ float g_qin[Mc*256];   // [M,256] query concat
__device__ float g_X  [Mc*256];   // [M,256] relu(cat @ Win + b)
__device__ float g_q  [Mc*Ec];    // [B,H,S,HD]
__device__ float g_k  [Mc*Ec];    // [B,H,S,HD]
__device__ float g_v  [Mc*Ec];    // [B,H,S,HD]
__device__ float g_Zp [Bc*Hc*Sc]; // per (b,h,i) sum of exp(score), j<=i
__device__ float g_O  [Mc*Ec];    // [B,H,S,HD] attention output

// ---------------- 1) gather + build inputs ----------------
__global__ void prep_kernel(const int* __restrict__ item_in, const int* __restrict__ skill_in,
                            const int* __restrict__ label_in, const int* __restrict__ item_ids,
                            const int* __restrict__ skill_ids, const float* __restrict__ item_emb,
                            const float* __restrict__ skill_emb)
{
    int m = blockIdx.x;
    int d = threadIdx.x;                 // 0..127
    int y = label_in[m];
    float it = item_emb[(size_t)item_in[m]*Ec + d];
    float sk = skill_emb[(size_t)skill_in[m]*Ec + d];
    float* c = g_cat + (size_t)m*512;
    c[d]       = y ? it : 0.f;
    c[128 + d] = y ? 0.f : it;
    c[256 + d] = y ? sk : 0.f;
    c[384 + d] = y ? 0.f : sk;
    float* qn = g_qin + (size_t)m*256;
    qn[d]       = item_emb[(size_t)item_ids[m]*Ec + d];
    qn[128 + d] = skill_emb[(size_t)skill_ids[m]*Ec + d];
}

// ---------------- 2) generic tiled fp32 GEMM: out = act(A[M,K] @ W[K,N] + b) ----------------
// asel: 0=g_cat 1=g_qin 2=g_X ; osel: 0=g_X(row-major) 1=g_q 2=g_k 3=g_v (head-major)
template<int KDIM, int NDIM, int RELU, int HEADOUT>
__global__ __launch_bounds__(256) void gemm_kernel(int asel, const float* __restrict__ W,
                                                   const float* __restrict__ bias, int osel)
{
    __shared__ float AsT[16][68];   // [k][m], padded
    __shared__ float Ws [16][64];   // [k][n]
    const float* A = (asel == 0) ? g_cat : (asel == 1) ? g_qin : g_X;
    float* out = (osel == 0) ? g_X : (osel == 1) ? g_q : (osel == 2) ? g_k : g_v;

    int tid = threadIdx.x;
    int m0 = blockIdx.y * 64;
    int n0 = blockIdx.x * 64;
    int tx = tid & 15, ty = tid >> 4;
    int r0 = ty * 4, c0 = tx * 4;
    int arow = tid >> 2,  acg = (tid & 3) * 4;
    int wrow = tid >> 4,  wcg = (tid & 15) * 4;

    float acc[4][4];
    #pragma unroll
    for (int i = 0; i < 4; i++)
        #pragma unroll
        for (int j = 0; j < 4; j++) acc[i][j] = 0.f;

    for (int kt = 0; kt < KDIM; kt += 16) {
        float4 av = *(const float4*)&A[(size_t)(m0 + arow)*KDIM + kt + acg];
        float4 wv = *(const float4*)&W[(size_t)(kt + wrow)*NDIM + n0 + wcg];
        __syncthreads();
        AsT[acg+0][arow] = av.x; AsT[acg+1][arow] = av.y;
        AsT[acg+2][arow] = av.z; AsT[acg+3][arow] = av.w;
        *(float4*)&Ws[wrow][wcg] = wv;
        __syncthreads();
        #pragma unroll
        for (int kk = 0; kk < 16; kk++) {
            float4 a4 = *(float4*)&AsT[kk][r0];
            float4 w4 = *(float4*)&Ws[kk][c0];
            float aa[4] = {a4.x, a4.y, a4.z, a4.w};
            float ww[4] = {w4.x, w4.y, w4.z, w4.w};
            #pragma unroll
            for (int ri = 0; ri < 4; ri++)
                #pragma unroll
                for (int ci = 0; ci < 4; ci++)
                    acc[ri][ci] = fmaf(aa[ri], ww[ci], acc[ri][ci]);
        }
    }

    float4 bv = *(const float4*)&bias[n0 + c0];
    float bb[4] = {bv.x, bv.y, bv.z, bv.w};
    #pragma unroll
    for (int ri = 0; ri < 4; ri++) {
        float4 o;
        float v0 = acc[ri][0] + bb[0];
        float v1 = acc[ri][1] + bb[1];
        float v2 = acc[ri][2] + bb[2];
        float v3 = acc[ri][3] + bb[3];
        if (RELU) { v0 = fmaxf(v0,0.f); v1 = fmaxf(v1,0.f); v2 = fmaxf(v2,0.f); v3 = fmaxf(v3,0.f); }
        o.x = v0; o.y = v1; o.z = v2; o.w = v3;
        int r = m0 + r0 + ri;
        if (!HEADOUT) {
            *(float4*)&out[(size_t)r*NDIM + n0 + c0] = o;
        } else {
            int b = r >> 11, s = r & 2047;
            int n = n0 + c0;
            int h = n >> 5, d = n & 31;
            *(float4*)&out[(((size_t)(b*Hc + h))*Sc + s)*HDc + d] = o;
        }
    }
}

// ---------------- 3) causal QK: write exp(q.k/sqrt(32)) raw + per-row sums ----------------
__global__ __launch_bounds__(256) void qk_kernel(float* __restrict__ prob)
{
    __shared__ float qsT[32][68];
    __shared__ float ksT[32][68];
    __shared__ float red[16][65];
    int tid = threadIdx.x;
    int it = blockIdx.x;      // q-tile (0..31)
    int bh = blockIdx.y;      // 0..15
    int i0 = it * 64;
    const float* qp = g_q + (size_t)bh * Sc * HDc;
    const float* kp = g_k + (size_t)bh * Sc * HDc;

    #pragma unroll
    for (int t = 0; t < 2; t++) {
        int idx = tid + t * 256;
        int r = idx >> 3, dg = (idx & 7) * 4;
        float4 v = *(const float4*)&qp[(size_t)(i0 + r)*HDc + dg];
        qsT[dg+0][r] = v.x; qsT[dg+1][r] = v.y; qsT[dg+2][r] = v.z; qsT[dg+3][r] = v.w;
    }

    int tx = tid & 15, ty = tid >> 4;
    int r0 = ty * 4, c0 = tx * 4;
    float rs[4] = {0.f, 0.f, 0.f, 0.f};
    const float scale = 0.17677669529663687f;   // 1/sqrt(32)

    for (int jt = 0; jt <= it; jt++) {
        int j0 = jt * 64;
        __syncthreads();
        #pragma unroll
        for (int t = 0; t < 2; t++) {
            int idx = tid + t * 256;
            int r = idx >> 3, dg = (idx & 7) * 4;
            float4 v = *(const float4*)&kp[(size_t)(j0 + r)*HDc + dg];
            ksT[dg+0][r] = v.x; ksT[dg+1][r] = v.y; ksT[dg+2][r] = v.z; ksT[dg+3][r] = v.w;
        }
        __syncthreads();

        float acc[4][4];
        #pragma unroll
        for (int i = 0; i < 4; i++)
            #pragma unroll
            for (int j = 0; j < 4; j++) acc[i][j] = 0.f;

        #pragma unroll
        for (int kk = 0; kk < 32; kk++) {
            float4 a4 = *(float4*)&qsT[kk][r0];
            float4 b4 = *(float4*)&ksT[kk][c0];
            float aa[4] = {a4.x, a4.y, a4.z, a4.w};
            float bb[4] = {b4.x, b4.y, b4.z, b4.w};
            #pragma unroll
            for (int ri = 0; ri < 4; ri++)
                #pragma unroll
                for (int ci = 0; ci < 4; ci++)
                    acc[ri][ci] = fmaf(aa[ri], bb[ci], acc[ri][ci]);
        }

        bool diag = (jt == it);
        #pragma unroll
        for (int ri = 0; ri < 4; ri++) {
            int i = i0 + r0 + ri;
            float ev[4];
            #pragma unroll
            for (int ci = 0; ci < 4; ci++) {
                int j = j0 + c0 + ci;
                bool valid = (!diag) || (j <= i);
                float e = valid ? __expf(acc[ri][ci] * scale) : 0.f;
                rs[ri] += e;
                ev[ci] = e;
            }
            float4 o; o.x = ev[0]; o.y = ev[1]; o.z = ev[2]; o.w = ev[3];
            *(float4*)&prob[(size_t)bh*SSs + (size_t)i*Sc + j0 + c0] = o;
        }
    }

    __syncthreads();
    #pragma unroll
    for (int ri = 0; ri < 4; ri++) red[tx][r0 + ri] = rs[ri];
    __syncthreads();
    if (tid < 64) {
        float z = 0.f;
        #pragma unroll
        for (int t = 0; t < 16; t++) z += red[t][tid];
        g_Zp[bh*Sc + i0 + tid] = z;
    }
}

// ---------------- 4) combine: time/rel softmax + blend + normalize, writes all heads ----------------
__global__ __launch_bounds__(256) void combine_kernel(const float* __restrict__ rel,
        const float* __restrict__ ts, const float* __restrict__ l1p,
        const float* __restrict__ l2p, float* __restrict__ prob)
{
    __shared__ float e[Sc];
    __shared__ float szt[8], szr[8];
    int bi = blockIdx.x;                 // row id = b*S + i
    int b = bi >> 11, i = bi & 2047;
    int tid = threadIdx.x;
    const float* tsr = ts  + (size_t)bi * Sc;
    const float* rlr = rel + (size_t)bi * Sc;

    float zt = 0.f, zr = 0.f;
    for (int j = tid; j < Sc; j += 256) {
        if (j <= i) {
            float u = __expf(-fabsf(tsr[j]));
            float v = __expf(u);
            e[j] = v; zt += v;
        } else {
            float rv = rlr[j];
            float v = (rv == 0.f) ? 0.f : __expf(rv);   // rel==0 -> masked to -10000 in ref -> 0
            e[j] = v; zr += v;
        }
    }
    #pragma unroll
    for (int o = 16; o; o >>= 1) {
        zt += __shfl_xor_sync(0xffffffffu, zt, o);
        zr += __shfl_xor_sync(0xffffffffu, zr, o);
    }
    if ((tid & 31) == 0) { szt[tid >> 5] = zt; szr[tid >> 5] = zr; }
    __syncthreads();
    zt = 0.f; zr = 0.f;
    #pragma unroll
    for (int w = 0; w < 8; w++) { zt += szt[w]; zr += szr[w]; }

    float l1 = *l1p, l2 = *l2p;
    float ct = (1.f - l1) * l2 / zt;
    float cr = 0.f, uni = 0.f;
    if (i == Sc - 1) uni = l1 / (float)Sc;   // all rel logits masked -> uniform softmax
    else             cr  = l1 / zr;
    float cp[4];
    #pragma unroll
    for (int h = 0; h < 4; h++)
        cp[h] = (1.f - l1) * (1.f - l2) / g_Zp[(b*Hc + h)*Sc + i];

    size_t base0 = (size_t)(b*Hc)*SSs + (size_t)i*Sc;
    for (int j = tid; j < Sc; j += 256) {
        if (j <= i) {
            float add = ct * e[j] + uni;
            #pragma unroll
            for (int h = 0; h < 4; h++) {
                size_t a = base0 + (size_t)h*SSs + j;
                prob[a] = cp[h] * prob[a] + add;
            }
        } else {
            float v = cr * e[j];
            #pragma unroll
            for (int h = 0; h < 4; h++) prob[base0 + (size_t)h*SSs + j] = v;
        }
    }
}

// ---------------- 5) AV: O[b,h,i,d] = sum_j prob[b,h,i,j] * v[b,h,j,d] ----------------
__global__ __launch_bounds__(128) void av_kernel(const float* __restrict__ prob)
{
    __shared__ float PsT[32][68];   // [j][i]
    __shared__ float Vs [32][32];   // [j][d]
    int tid = threadIdx.x;
    int it = blockIdx.x, bh = blockIdx.y;
    int i0 = it * 64;
    const float* pp = prob + (size_t)bh * SSs;
    const float* vp = g_v  + (size_t)bh * Sc * HDc;
    int tx = tid & 7, ty = tid >> 3;       // 8 x 16
    int r0 = ty * 4, c0 = tx * 4;

    float acc[4][4];
    #pragma unroll
    for (int i = 0; i < 4; i++)
        #pragma unroll
        for (int j = 0; j < 4; j++) acc[i][j] = 0.f;

    for (int jt = 0; jt < Sc / 32; jt++) {
        int j0 = jt * 32;
        __syncthreads();
        #pragma unroll
        for (int t = 0; t < 4; t++) {
            int idx = tid + t * 128;
            int r = idx >> 3, cg = (idx & 7) * 4;
            float4 v = *(const float4*)&pp[(size_t)(i0 + r)*Sc + j0 + cg];
            PsT[cg+0][r] = v.x; PsT[cg+1][r] = v.y; PsT[cg+2][r] = v.z; PsT[cg+3][r] = v.w;
        }
        #pragma unroll
        for (int t = 0; t < 2; t++) {
            int idx = tid + t * 128;
            int r = idx >> 3, cg = (idx & 7) * 4;
            *(float4*)&Vs[r][cg] = *(const float4*)&vp[(size_t)(j0 + r)*HDc + cg];
        }
        __syncthreads();
        #pragma unroll
        for (int kk = 0; kk < 32; kk++) {
            float4 a4 = *(float4*)&PsT[kk][r0];
            float4 b4 = *(float4*)&Vs[kk][c0];
            float aa[4] = {a4.x, a4.y, a4.z, a4.w};
            float bb[4] = {b4.x, b4.y, b4.z, b4.w};
            #pragma unroll
            for (int ri = 0; ri < 4; ri++)
                #pragma unroll
                for (int ci = 0; ci < 4; ci++)
                    acc[ri][ci] = fmaf(aa[ri], bb[ci], acc[ri][ci]);
        }
    }
    #pragma unroll
    for (int ri = 0; ri < 4; ri++) {
        float4 o; o.x = acc[ri][0]; o.y = acc[ri][1]; o.z = acc[ri][2]; o.w = acc[ri][3];
        *(float4*)&g_O[(size_t)(bh*Sc + i0 + r0 + ri)*HDc + c0] = o;
    }
}

// ---------------- 6) pred = O @ Wout + bout ----------------
__global__ void pred_kernel(const float* __restrict__ Wout, const float* __restrict__ bout,
                            float* __restrict__ pred)
{
    __shared__ float sm[4];
    int m = blockIdx.x;
    int tid = threadIdx.x;           // 128 = e index (h*32+d)
    int b = m >> 11, s = m & 2047;
    int h = tid >> 5, d = tid & 31;
    float v = g_O[(((size_t)(b*Hc + h))*Sc + s)*HDc + d] * Wout[tid];
    #pragma unroll
    for (int o = 16; o; o >>= 1) v += __shfl_xor_sync(0xffffffffu, v, o);
    if ((tid & 31) == 0) sm[tid >> 5] = v;
    __syncthreads();
    if (tid == 0) pred[m] = sm[0] + sm[1] + sm[2] + sm[3] + bout[0];
}

// ---------------- launch ----------------
extern "C" void kernel_launch(void* const* d_in, const int* in_sizes, int n_in,
                              void* d_out, int out_size)
{
    (void)in_sizes; (void)n_in; (void)out_size;
    const int*   item_inputs  = (const int*)  d_in[0];
    const int*   skill_inputs = (const int*)  d_in[1];
    const int*   label_inputs = (const int*)  d_in[2];
    const int*   item_ids     = (const int*)  d_in[3];
    const int*   skill_ids    = (const int*)  d_in[4];
    const float* rel          = (const float*)d_in[5];
    const float* ts           = (const float*)d_in[6];
    const float* item_emb     = (const float*)d_in[7];
    const float* skill_emb    = (const float*)d_in[8];
    const float* Win          = (const float*)d_in[9];
    const float* b_in         = (const float*)d_in[10];
    const float* Wq           = (const float*)d_in[11];
    const float* bq           = (const float*)d_in[12];
    const float* Wk           = (const float*)d_in[13];
    const float* bk           = (const float*)d_in[14];
    const float* Wv           = (const float*)d_in[15];
    const float* bv           = (const float*)d_in[16];
    const float* Wout         = (const float*)d_in[17];
    const float* bout         = (const float*)d_in[18];
    const float* l1           = (const float*)d_in[19];
    const float* l2           = (const float*)d_in[20];

    float* pred = (float*)d_out;
    float* prob = pred + Mc;          // pred [8192] then prob_attn [B,H,S,S]

    prep_kernel<<<Mc, 128>>>(item_inputs, skill_inputs, label_inputs,
                             item_ids, skill_ids, item_emb, skill_emb);
    gemm_kernel<512, 256, 1, 0><<<dim3(4, 128), 256>>>(0, Win, b_in, 0);  // X = relu(cat@Win+b)
    gemm_kernel<256, 128, 0, 1><<<dim3(2, 128), 256>>>(1, Wq, bq, 1);     // q
    gemm_kernel<256, 128, 0, 1><<<dim3(2, 128), 256>>>(2, Wk, bk, 2);     // k
    gemm_kernel<256, 128, 0, 1><<<dim3(2, 128), 256>>>(2, Wv, bv, 3);     // v
    qk_kernel<<<dim3(32, 16), 256>>>(prob);
    combine_kernel<<<Mc, 256>>>(rel, ts, l1, l2, prob);
    av_kernel<<<dim3(32, 16), 128>>>(prob);
    pred_kernel<<<Mc, 128>>>(Wout, bout, pred);
}

// round 4
// speedup vs baseline: 1.6506x; 1.6506x over previous
#include <cuda_runtime.h>
#include <math.h>
#include <stdint.h>

#define Bc 4
#define Sc 2048
#define Ec 128
#define Hc 4
#define HDc 32
#define Mc (Bc*Sc)            // 8192 tokens
#define SSs ((size_t)Sc*(size_t)Sc)

// ---------------- scratch (device globals: allocation-free) ----------------
__device__ float g_cat[Mc*512];   // [M,512] gated concat input
__device__ float g_qin[Mc*256];   // [M,256] query concat
__device__ float g_X  [Mc*256];   // [M,256] relu(cat @ Win + b)
__device__ float g_q  [Mc*Ec];    // [B,H,S,HD]
__device__ float g_k  [Mc*Ec];    // [B,H,S,HD]
__device__ float g_v  [Mc*Ec];    // [B,H,S,HD]
__device__ float g_Zp [Bc*Hc*Sc]; // per (b,h,i) sum of exp(score), j<=i
__device__ float g_O  [Mc*Ec];    // [B,H,S,HD] attention output

// ---------------- tf32 helpers ----------------
__device__ __forceinline__ uint32_t f2tf(float x) {
    uint32_t r; asm("cvt.rna.tf32.f32 %0, %1;" : "=r"(r) : "f"(x)); return r;
}
__device__ __forceinline__ void mma_tf32(float (&d)[4], const uint32_t (&a)[4],
                                         const uint32_t (&b)[2]) {
    asm volatile("mma.sync.aligned.m16n8k8.row.col.f32.tf32.tf32.f32 "
        "{%0,%1,%2,%3}, {%4,%5,%6,%7}, {%8,%9}, {%0,%1,%2,%3};\n"
        : "+f"(d[0]), "+f"(d[1]), "+f"(d[2]), "+f"(d[3])
        : "r"(a[0]), "r"(a[1]), "r"(a[2]), "r"(a[3]), "r"(b[0]), "r"(b[1]));
}

// ---------------- 1) gather + build inputs ----------------
__global__ void prep_kernel(const int* __restrict__ item_in, const int* __restrict__ skill_in,
                            const int* __restrict__ label_in, const int* __restrict__ item_ids,
                            const int* __restrict__ skill_ids, const float* __restrict__ item_emb,
                            const float* __restrict__ skill_emb)
{
    int m = blockIdx.x;
    int d = threadIdx.x;                 // 0..127
    int y = label_in[m];
    float it = item_emb[(size_t)item_in[m]*Ec + d];
    float sk = skill_emb[(size_t)skill_in[m]*Ec + d];
    float* c = g_cat + (size_t)m*512;
    c[d]       = y ? it : 0.f;
    c[128 + d] = y ? 0.f : it;
    c[256 + d] = y ? sk : 0.f;
    c[384 + d] = y ? 0.f : sk;
    float* qn = g_qin + (size_t)m*256;
    qn[d]       = item_emb[(size_t)item_ids[m]*Ec + d];
    qn[128 + d] = skill_emb[(size_t)skill_ids[m]*Ec + d];
}

// ---------------- 2) tf32 MMA GEMM: out = act(A[M,K] @ W[K,N] + b) ----------------
// BM=128, BN=64, BK=32, 256 threads (8 warps: 4 along M x 2 along N, warp tile 32x32)
template<int KDIM, int NDIM, int RELU, int HEADOUT>
__global__ __launch_bounds__(256) void mm_kernel(int asel, const float* __restrict__ W,
                                                 const float* __restrict__ bias, int osel)
{
    __shared__ uint32_t As[128][36];   // [m][k] pad -> bank (4g+c)
    __shared__ uint32_t Bs[32][72];    // [k][n] pad -> bank (8k+n)
    const float* A = (asel == 0) ? g_cat : (asel == 1) ? g_qin : g_X;
    float* out = (osel == 0) ? g_X : (osel == 1) ? g_q : (osel == 2) ? g_k : g_v;

    int tid = threadIdx.x;
    int m0 = blockIdx.y * 128;
    int n0 = blockIdx.x * 64;
    int w = tid >> 5, lane = tid & 31;
    int g = lane >> 2, tg = lane & 3;
    int wm = w & 3, wn = w >> 2;

    float acc[2][4][4];
    #pragma unroll
    for (int mi = 0; mi < 2; mi++)
        #pragma unroll
        for (int ni = 0; ni < 4; ni++)
            #pragma unroll
            for (int r = 0; r < 4; r++) acc[mi][ni][r] = 0.f;

    for (int kt = 0; kt < KDIM; kt += 32) {
        float4 av[4]; float4 wv[2];
        #pragma unroll
        for (int t = 0; t < 4; t++) {
            int idx = tid + t*256;
            int r = idx >> 3, c = (idx & 7) * 4;
            av[t] = *(const float4*)&A[(size_t)(m0 + r)*KDIM + kt + c];
        }
        #pragma unroll
        for (int t = 0; t < 2; t++) {
            int idx = tid + t*256;
            int r = idx >> 4, c = (idx & 15) * 4;
            wv[t] = *(const float4*)&W[(size_t)(kt + r)*NDIM + n0 + c];
        }
        __syncthreads();
        #pragma unroll
        for (int t = 0; t < 4; t++) {
            int idx = tid + t*256;
            int r = idx >> 3, c = (idx & 7) * 4;
            uint4 u = { f2tf(av[t].x), f2tf(av[t].y), f2tf(av[t].z), f2tf(av[t].w) };
            *(uint4*)&As[r][c] = u;
        }
        #pragma unroll
        for (int t = 0; t < 2; t++) {
            int idx = tid + t*256;
            int r = idx >> 4, c = (idx & 15) * 4;
            uint4 u = { f2tf(wv[t].x), f2tf(wv[t].y), f2tf(wv[t].z), f2tf(wv[t].w) };
            *(uint4*)&Bs[r][c] = u;
        }
        __syncthreads();

        #pragma unroll
        for (int kk = 0; kk < 4; kk++) {
            uint32_t a[2][4], b[4][2];
            #pragma unroll
            for (int mi = 0; mi < 2; mi++) {
                int r = wm*32 + mi*16 + g;
                a[mi][0] = As[r][kk*8 + tg];
                a[mi][1] = As[r + 8][kk*8 + tg];
                a[mi][2] = As[r][kk*8 + tg + 4];
                a[mi][3] = As[r + 8][kk*8 + tg + 4];
            }
            #pragma unroll
            for (int ni = 0; ni < 4; ni++) {
                int c = wn*32 + ni*8 + g;
                b[ni][0] = Bs[kk*8 + tg][c];
                b[ni][1] = Bs[kk*8 + tg + 4][c];
            }
            #pragma unroll
            for (int mi = 0; mi < 2; mi++)
                #pragma unroll
                for (int ni = 0; ni < 4; ni++)
                    mma_tf32(acc[mi][ni], a[mi], b[ni]);
        }
        __syncthreads();
    }

    #pragma unroll
    for (int mi = 0; mi < 2; mi++) {
        int rl = m0 + wm*32 + mi*16 + g;
        int rh = rl + 8;
        #pragma unroll
        for (int ni = 0; ni < 4; ni++) {
            int c = n0 + wn*32 + ni*8 + 2*tg;
            float b0 = bias[c], b1 = bias[c+1];
            float v00 = acc[mi][ni][0] + b0, v01 = acc[mi][ni][1] + b1;
            float v10 = acc[mi][ni][2] + b0, v11 = acc[mi][ni][3] + b1;
            if (RELU) {
                v00 = fmaxf(v00, 0.f); v01 = fmaxf(v01, 0.f);
                v10 = fmaxf(v10, 0.f); v11 = fmaxf(v11, 0.f);
            }
            float2 lo = {v00, v01}, hi = {v10, v11};
            if (!HEADOUT) {
                *(float2*)&out[(size_t)rl*NDIM + c] = lo;
                *(float2*)&out[(size_t)rh*NDIM + c] = hi;
            } else {
                int h = c >> 5, d = c & 31;
                *(float2*)&out[(((size_t)((rl >> 11)*Hc + h))*Sc + (rl & 2047))*HDc + d] = lo;
                *(float2*)&out[(((size_t)((rh >> 11)*Hc + h))*Sc + (rh & 2047))*HDc + d] = hi;
            }
        }
    }
}

// ---------------- 3) causal QK (tf32 mma): write exp(q.k/sqrt(32)) raw + row sums ----------------
// grid (32 i-tiles, 16 bh), 256 threads; tile 64(i) x 64(j); warps: 2 along i x 4 along j
__global__ __launch_bounds__(256) void qk_kernel(float* __restrict__ prob)
{
    __shared__ uint32_t Qs[64][36];
    __shared__ uint32_t Ks[64][36];
    __shared__ float red[64][4];
    int tid = threadIdx.x;
    int it = blockIdx.x, bh = blockIdx.y;
    int i0 = it * 64;
    const float* qp = g_q + (size_t)bh * Sc * HDc;
    const float* kp = g_k + (size_t)bh * Sc * HDc;
    size_t pb = (size_t)bh * SSs;

    int w = tid >> 5, lane = tid & 31;
    int g = lane >> 2, tg = lane & 3;
    int wm = w & 1, wn = w >> 1;        // warp tile 32(i) x 16(j)

    // load Q tile 64x32
    #pragma unroll
    for (int t = 0; t < 2; t++) {
        int idx = tid + t*256;
        int r = idx >> 3, c = (idx & 7) * 4;
        float4 v = *(const float4*)&qp[(size_t)(i0 + r)*HDc + c];
        uint4 u = { f2tf(v.x), f2tf(v.y), f2tf(v.z), f2tf(v.w) };
        *(uint4*)&Qs[r][c] = u;
    }

    float rs[2][2] = {{0.f,0.f},{0.f,0.f}};
    const float scale = 0.17677669529663687f;   // 1/sqrt(32)

    for (int jt = 0; jt <= it; jt++) {
        int j0 = jt * 64;
        float4 kv[2];
        #pragma unroll
        for (int t = 0; t < 2; t++) {
            int idx = tid + t*256;
            int r = idx >> 3, c = (idx & 7) * 4;
            kv[t] = *(const float4*)&kp[(size_t)(j0 + r)*HDc + c];
        }
        __syncthreads();
        #pragma unroll
        for (int t = 0; t < 2; t++) {
            int idx = tid + t*256;
            int r = idx >> 3, c = (idx & 7) * 4;
            uint4 u = { f2tf(kv[t].x), f2tf(kv[t].y), f2tf(kv[t].z), f2tf(kv[t].w) };
            *(uint4*)&Ks[r][c] = u;
        }
        __syncthreads();

        float acc[2][2][4];
        #pragma unroll
        for (int mi = 0; mi < 2; mi++)
            #pragma unroll
            for (int ni = 0; ni < 2; ni++)
                #pragma unroll
                for (int r = 0; r < 4; r++) acc[mi][ni][r] = 0.f;

        #pragma unroll
        for (int kk = 0; kk < 4; kk++) {
            uint32_t a[2][4], b[2][2];
            #pragma unroll
            for (int mi = 0; mi < 2; mi++) {
                int r = wm*32 + mi*16 + g;
                a[mi][0] = Qs[r][kk*8 + tg];
                a[mi][1] = Qs[r + 8][kk*8 + tg];
                a[mi][2] = Qs[r][kk*8 + tg + 4];
                a[mi][3] = Qs[r + 8][kk*8 + tg + 4];
            }
            #pragma unroll
            for (int ni = 0; ni < 2; ni++) {
                int c = wn*16 + ni*8 + g;      // j index acts as "n"
                b[ni][0] = Ks[c][kk*8 + tg];
                b[ni][1] = Ks[c][kk*8 + tg + 4];
            }
            #pragma unroll
            for (int mi = 0; mi < 2; mi++)
                #pragma unroll
                for (int ni = 0; ni < 2; ni++)
                    mma_tf32(acc[mi][ni], a[mi], b[ni]);
        }

        bool dg = (jt == it);
        #pragma unroll
        for (int mi = 0; mi < 2; mi++) {
            int rl = i0 + wm*32 + mi*16 + g;
            int rh = rl + 8;
            #pragma unroll
            for (int ni = 0; ni < 2; ni++) {
                int cl = j0 + wn*16 + ni*8 + 2*tg;
                float e0 = (!dg || cl     <= rl) ? __expf(acc[mi][ni][0]*scale) : 0.f;
                float e1 = (!dg || cl + 1 <= rl) ? __expf(acc[mi][ni][1]*scale) : 0.f;
                float e2 = (!dg || cl     <= rh) ? __expf(acc[mi][ni][2]*scale) : 0.f;
                float e3 = (!dg || cl + 1 <= rh) ? __expf(acc[mi][ni][3]*scale) : 0.f;
                rs[mi][0] += e0 + e1;
                rs[mi][1] += e2 + e3;
                float2 lo = {e0, e1}, hi = {e2, e3};
                *(float2*)&prob[pb + (size_t)rl*Sc + cl] = lo;
                *(float2*)&prob[pb + (size_t)rh*Sc + cl] = hi;
            }
        }
        __syncthreads();
    }

    // reduce row sums: 4 threads (tg) share a row within warp; 4 j-warps duplicate
    #pragma unroll
    for (int mi = 0; mi < 2; mi++)
        #pragma unroll
        for (int hf = 0; hf < 2; hf++) {
            float v = rs[mi][hf];
            v += __shfl_xor_sync(0xffffffffu, v, 1);
            v += __shfl_xor_sync(0xffffffffu, v, 2);
            if (tg == 0) red[wm*32 + mi*16 + g + hf*8][wn] = v;
        }
    __syncthreads();
    if (tid < 64) {
        float z = red[tid][0] + red[tid][1] + red[tid][2] + red[tid][3];
        g_Zp[bh*Sc + i0 + tid] = z;
    }
}

// ---------------- 4) combine: time/rel softmax + blend + normalize (float4 vectorized) ----------------
__global__ __launch_bounds__(256) void combine_kernel(const float* __restrict__ rel,
        const float* __restrict__ ts, const float* __restrict__ l1p,
        const float* __restrict__ l2p, float* __restrict__ prob)
{
    __shared__ float szt[8], szr[8];
    int bi = blockIdx.x;                 // row id = b*S + i
    int b = bi >> 11, i = bi & 2047;
    int tid = threadIdx.x;
    const float* tsr = ts  + (size_t)bi * Sc;
    const float* rlr = rel + (size_t)bi * Sc;

    float ev[2][4];
    float zt = 0.f, zr = 0.f;
    #pragma unroll
    for (int t = 0; t < 2; t++) {
        int j = tid*4 + t*1024;
        if (j + 3 <= i) {
            float4 tv = *(const float4*)&tsr[j];
            float v0 = __expf(__expf(-fabsf(tv.x)));
            float v1 = __expf(__expf(-fabsf(tv.y)));
            float v2 = __expf(__expf(-fabsf(tv.z)));
            float v3 = __expf(__expf(-fabsf(tv.w)));
            ev[t][0]=v0; ev[t][1]=v1; ev[t][2]=v2; ev[t][3]=v3;
            zt += (v0+v1) + (v2+v3);
        } else if (j > i) {
            float4 rv = *(const float4*)&rlr[j];
            float v0 = (rv.x == 0.f) ? 0.f : __expf(rv.x);
            float v1 = (rv.y == 0.f) ? 0.f : __expf(rv.y);
            float v2 = (rv.z == 0.f) ? 0.f : __expf(rv.z);
            float v3 = (rv.w == 0.f) ? 0.f : __expf(rv.w);
            ev[t][0]=v0; ev[t][1]=v1; ev[t][2]=v2; ev[t][3]=v3;
            zr += (v0+v1) + (v2+v3);
        } else {
            #pragma unroll
            for (int u = 0; u < 4; u++) {
                int jj = j + u;
                if (jj <= i) {
                    float v = __expf(__expf(-fabsf(tsr[jj])));
                    ev[t][u] = v; zt += v;
                } else {
                    float rv = rlr[jj];
                    float v = (rv == 0.f) ? 0.f : __expf(rv);
                    ev[t][u] = v; zr += v;
                }
            }
        }
    }
    #pragma unroll
    for (int o = 16; o; o >>= 1) {
        zt += __shfl_xor_sync(0xffffffffu, zt, o);
        zr += __shfl_xor_sync(0xffffffffu, zr, o);
    }
    if ((tid & 31) == 0) { szt[tid >> 5] = zt; szr[tid >> 5] = zr; }
    __syncthreads();
    zt = 0.f; zr = 0.f;
    #pragma unroll
    for (int wi = 0; wi < 8; wi++) { zt += szt[wi]; zr += szr[wi]; }

    float l1 = *l1p, l2 = *l2p;
    float ct = (1.f - l1) * l2 / zt;
    float cr = 0.f, uni = 0.f;
    if (i == Sc - 1) uni = l1 / (float)Sc;   // all rel logits masked -> uniform softmax
    else             cr  = l1 / zr;
    float cp[4];
    #pragma unroll
    for (int h = 0; h < 4; h++)
        cp[h] = (1.f - l1) * (1.f - l2) / g_Zp[(b*Hc + h)*Sc + i];

    size_t base0 = (size_t)(b*Hc)*SSs + (size_t)i*Sc;
    #pragma unroll
    for (int t = 0; t < 2; t++) {
        int j = tid*4 + t*1024;
        if (j + 3 <= i) {
            float a0 = ct*ev[t][0] + uni, a1 = ct*ev[t][1] + uni;
            float a2 = ct*ev[t][2] + uni, a3 = ct*ev[t][3] + uni;
            #pragma unroll
            for (int h = 0; h < 4; h++) {
                size_t a = base0 + (size_t)h*SSs + j;
                float4 p = *(float4*)&prob[a];
                p.x = cp[h]*p.x + a0; p.y = cp[h]*p.y + a1;
                p.z = cp[h]*p.z + a2; p.w = cp[h]*p.w + a3;
                *(float4*)&prob[a] = p;
            }
        } else if (j > i) {
            float4 v = { cr*ev[t][0], cr*ev[t][1], cr*ev[t][2], cr*ev[t][3] };
            #pragma unroll
            for (int h = 0; h < 4; h++)
                *(float4*)&prob[base0 + (size_t)h*SSs + j] = v;
        } else {
            #pragma unroll
            for (int u = 0; u < 4; u++) {
                int jj = j + u;
                if (jj <= i) {
                    float add = ct*ev[t][u] + uni;
                    #pragma unroll
                    for (int h = 0; h < 4; h++) {
                        size_t a = base0 + (size_t)h*SSs + jj;
                        prob[a] = cp[h]*prob[a] + add;
                    }
                } else {
                    float v = cr*ev[t][u];
                    #pragma unroll
                    for (int h = 0; h < 4; h++)
                        prob[base0 + (size_t)h*SSs + jj] = v;
                }
            }
        }
    }
}

// ---------------- 5) AV (tf32 mma): O[b,h,i,d] = sum_j prob[b,h,i,j] * v[b,h,j,d] ----------------
// grid (32 i-tiles, 16 bh), 256 threads; tile 64(i) x 32(d), BK=64; warps: 4 along i x 2 along d
__global__ __launch_bounds__(256) void av_kernel(const float* __restrict__ prob)
{
    __shared__ uint32_t Ps[64][68];   // [i][k]
    __shared__ uint32_t Vs[64][36];   // [k][d]
    int tid = threadIdx.x;
    int it = blockIdx.x, bh = blockIdx.y;
    int i0 = it * 64;
    const float* pp = prob + (size_t)bh * SSs;
    const float* vp = g_v  + (size_t)bh * Sc * HDc;

    int w = tid >> 5, lane = tid & 31;
    int g = lane >> 2, tg = lane & 3;
    int wm = w & 3, wn = w >> 2;      // warp tile 16(i) x 16(d)

    float acc[2][4];
    #pragma unroll
    for (int ni = 0; ni < 2; ni++)
        #pragma unroll
        for (int r = 0; r < 4; r++) acc[ni][r] = 0.f;

    for (int jt = 0; jt < Sc/64; jt++) {
        int j0 = jt * 64;
        float4 pv[4]; float4 vv[2];
        #pragma unroll
        for (int t = 0; t < 4; t++) {
            int idx = tid + t*256;
            int r = idx >> 4, c = (idx & 15) * 4;
            pv[t] = *(const float4*)&pp[(size_t)(i0 + r)*Sc + j0 + c];
        }
        #pragma unroll
        for (int t = 0; t < 2; t++) {
            int idx = tid + t*256;
            int r = idx >> 3, c = (idx & 7) * 4;
            vv[t] = *(const float4*)&vp[(size_t)(j0 + r)*HDc + c];
        }
        __syncthreads();
        #pragma unroll
        for (int t = 0; t < 4; t++) {
            int idx = tid + t*256;
            int r = idx >> 4, c = (idx & 15) * 4;
            uint4 u = { f2tf(pv[t].x), f2tf(pv[t].y), f2tf(pv[t].z), f2tf(pv[t].w) };
            *(uint4*)&Ps[r][c] = u;
        }
        #pragma unroll
        for (int t = 0; t < 2; t++) {
            int idx = tid + t*256;
            int r = idx >> 3, c = (idx & 7) * 4;
            uint4 u = { f2tf(vv[t].x), f2tf(vv[t].y), f2tf(vv[t].z), f2tf(vv[t].w) };
            *(uint4*)&Vs[r][c] = u;
        }
        __syncthreads();

        #pragma unroll
        for (int kk = 0; kk < 8; kk++) {
            uint32_t a[4], b[2][2];
            int r = wm*16 + g;
            a[0] = Ps[r][kk*8 + tg];
            a[1] = Ps[r + 8][kk*8 + tg];
            a[2] = Ps[r][kk*8 + tg + 4];
            a[3] = Ps[r + 8][kk*8 + tg + 4];
            #pragma unroll
            for (int ni = 0; ni < 2; ni++) {
                int c = wn*16 + ni*8 + g;
                b[ni][0] = Vs[kk*8 + tg][c];
                b[ni][1] = Vs[kk*8 + tg + 4][c];
            }
            #pragma unroll
            for (int ni = 0; ni < 2; ni++)
                mma_tf32(acc[ni], a, b[ni]);
        }
        __syncthreads();
    }

    int rl = i0 + wm*16 + g;
    int rh = rl + 8;
    #pragma unroll
    for (int ni = 0; ni < 2; ni++) {
        int c = wn*16 + ni*8 + 2*tg;
        float2 lo = {acc[ni][0], acc[ni][1]};
        float2 hi = {acc[ni][2], acc[ni][3]};
        *(float2*)&g_O[(size_t)(bh*Sc + rl)*HDc + c] = lo;
        *(float2*)&g_O[(size_t)(bh*Sc + rh)*HDc + c] = hi;
    }
}

// ---------------- 6) pred = O @ Wout + bout ----------------
__global__ void pred_kernel(const float* __restrict__ Wout, const float* __restrict__ bout,
                            float* __restrict__ pred)
{
    __shared__ float sm[4];
    int m = blockIdx.x;
    int tid = threadIdx.x;           // 128 = e index (h*32+d)
    int b = m >> 11, s = m & 2047;
    int h = tid >> 5, d = tid & 31;
    float v = g_O[(((size_t)(b*Hc + h))*Sc + s)*HDc + d] * Wout[tid];
    #pragma unroll
    for (int o = 16; o; o >>= 1) v += __shfl_xor_sync(0xffffffffu, v, o);
    if ((tid & 31) == 0) sm[tid >> 5] = v;
    __syncthreads();
    if (tid == 0) pred[m] = sm[0] + sm[1] + sm[2] + sm[3] + bout[0];
}

// ---------------- launch ----------------
extern "C" void kernel_launch(void* const* d_in, const int* in_sizes, int n_in,
                              void* d_out, int out_size)
{
    (void)in_sizes; (void)n_in; (void)out_size;
    const int*   item_inputs  = (const int*)  d_in[0];
    const int*   skill_inputs = (const int*)  d_in[1];
    const int*   label_inputs = (const int*)  d_in[2];
    const int*   item_ids     = (const int*)  d_in[3];
    const int*   skill_ids    = (const int*)  d_in[4];
    const float* rel          = (const float*)d_in[5];
    const float* ts           = (const float*)d_in[6];
    const float* item_emb     = (const float*)d_in[7];
    const float* skill_emb    = (const float*)d_in[8];
    const float* Win          = (const float*)d_in[9];
    const float* b_in         = (const float*)d_in[10];
    const float* Wq           = (const float*)d_in[11];
    const float* bq           = (const float*)d_in[12];
    const float* Wk           = (const float*)d_in[13];
    const float* bk           = (const float*)d_in[14];
    const float* Wv           = (const float*)d_in[15];
    const float* bv           = (const float*)d_in[16];
    const float* Wout         = (const float*)d_in[17];
    const float* bout         = (const float*)d_in[18];
    const float* l1           = (const float*)d_in[19];
    const float* l2           = (const float*)d_in[20];

    float* pred = (float*)d_out;
    float* prob = pred + Mc;          // pred [8192] then prob_attn [B,H,S,S]

    prep_kernel<<<Mc, 128>>>(item_inputs, skill_inputs, label_inputs,
                             item_ids, skill_ids, item_emb, skill_emb);
    mm_kernel<512, 256, 1, 0><<<dim3(4, 64), 256>>>(0, Win, b_in, 0);  // X = relu(cat@Win+b)
    mm_kernel<256, 128, 0, 1><<<dim3(2, 64), 256>>>(1, Wq, bq, 1);     // q
    mm_kernel<256, 128, 0, 1><<<dim3(2, 64), 256>>>(2, Wk, bk, 2);     // k
    mm_kernel<256, 128, 0, 1><<<dim3(2, 64), 256>>>(2, Wv, bv, 3);     // v
    qk_kernel<<<dim3(32, 16), 256>>>(prob);
    combine_kernel<<<Mc, 256>>>(rel, ts, l1, l2, prob);
    av_kernel<<<dim3(32, 16), 256>>>(prob);
    pred_kernel<<<Mc, 128>>>(Wout, bout, pred);
}